// round 6
// baseline (speedup 1.0000x reference)
#include <cuda_runtime.h>
#include <cuda_bf16.h>
#include <cstdint>

// out[b,m,c] = sum_{k<3} vals[m,k] * x[b, cols[m,k], c]
//   x: [8, 50000, 128] f32   cols: [25000, 3] i32   vals: [25000, 3] f32
//   out: [8, 25000, 128] f32
//
// Persistent, software-pipelined gather via cp.async:
//  - item = (batch-pair, m): 6 gather rows (512B each) -> 2 output rows
//  - cp.async.cg lands rows in SMEM (L2-cached: keeps the ~1.93x duplicate-
//    row reuse in L2, bypasses L1) WITHOUT pinning registers -> in-flight
//    bytes per SM ~96KB instead of the ~6KB register-file cap that held
//    DRAM at ~72% in earlier rounds.
//  - double-buffered per warp: issue item i+1's rows while computing item i.
//  - streaming .cs stores keep the write-once output out of L2.

#define B_DIM   8
#define N_DIM   50000
#define M_DIM   25000
#define C_VEC   32            // 128 floats / 4 per float4
#define BP      (B_DIM / 2)   // 4 batch pairs
#define NITEMS  (BP * M_DIM)  // 100000
#define WPB     8             // warps per block
#define THREADS 256
#define NBLOCKS (148 * 4)     // persistent: 4 CTAs per SM

__device__ __forceinline__ void cp16(float4* dst_smem, const float4* src) {
    unsigned saddr = (unsigned)__cvta_generic_to_shared(dst_smem);
    asm volatile("cp.async.cg.shared.global [%0], [%1], 16;"
                 :: "r"(saddr), "l"(src));
}

__device__ __forceinline__ void stcs(float4* p, float4 v) {
    asm volatile("st.global.cs.v4.f32 [%0], {%1,%2,%3,%4};"
                 :: "l"(p), "f"(v.x), "f"(v.y), "f"(v.z), "f"(v.w));
}

// Fetch indices/weights for item (bp, m) and issue its 6 row loads into dst.
__device__ __forceinline__ void issue_stage(float4 (*dst)[32],   // [6][32]
                                            const float4* __restrict__ x,
                                            const int*    __restrict__ cols,
                                            const float*  __restrict__ vals,
                                            int bp, int m, int lane,
                                            float& v0, float& v1, float& v2)
{
    const int c0 = __ldg(cols + m * 3 + 0);
    const int c1 = __ldg(cols + m * 3 + 1);
    const int c2 = __ldg(cols + m * 3 + 2);
    v0 = __ldg(vals + m * 3 + 0);
    v1 = __ldg(vals + m * 3 + 1);
    v2 = __ldg(vals + m * 3 + 2);

    const float4* xb0 = x + ((size_t)(2 * bp)     * N_DIM) * C_VEC + lane;
    const float4* xb1 = x + ((size_t)(2 * bp + 1) * N_DIM) * C_VEC + lane;

    cp16(&dst[0][lane], xb0 + (size_t)c0 * C_VEC);
    cp16(&dst[1][lane], xb0 + (size_t)c1 * C_VEC);
    cp16(&dst[2][lane], xb0 + (size_t)c2 * C_VEC);
    cp16(&dst[3][lane], xb1 + (size_t)c0 * C_VEC);
    cp16(&dst[4][lane], xb1 + (size_t)c1 * C_VEC);
    cp16(&dst[5][lane], xb1 + (size_t)c2 * C_VEC);
    asm volatile("cp.async.commit_group;");
}

__global__ __launch_bounds__(THREADS, 4)
void mesh_sampling_kernel(const float4* __restrict__ x,
                          const int*    __restrict__ cols,
                          const float*  __restrict__ vals,
                          float4*       __restrict__ out)
{
    // 2 stages x 8 warps x 6 rows x 32 lanes x 16B = 49152 B
    __shared__ float4 buf[2][WPB][6][32];

    const int lane = threadIdx.x & 31;
    const int wib  = threadIdx.x >> 5;
    const int gw   = blockIdx.x * WPB + wib;
    const int gstride = gridDim.x * WPB;

    int cur = gw;
    int bp_c = 0, m_c = 0;
    float w0c = 0.f, w1c = 0.f, w2c = 0.f;

    if (cur < NITEMS) {
        bp_c = cur / M_DIM;
        m_c  = cur - bp_c * M_DIM;
        issue_stage(buf[0][wib], x, cols, vals, bp_c, m_c, lane, w0c, w1c, w2c);
    }

    int phase = 0;
    while (cur < NITEMS) {
        const int nxt = cur + gstride;
        int bp_n = 0, m_n = 0;
        float w0n = 0.f, w1n = 0.f, w2n = 0.f;

        if (nxt < NITEMS) {
            bp_n = nxt / M_DIM;
            m_n  = nxt - bp_n * M_DIM;
            issue_stage(buf[phase ^ 1][wib], x, cols, vals, bp_n, m_n, lane,
                        w0n, w1n, w2n);
            // leave the newest group (next stage) in flight; current is done
            asm volatile("cp.async.wait_group 1;");
        } else {
            asm volatile("cp.async.wait_group 0;");
        }

        // consume current stage (each thread reads only what its own
        // cp.async wrote -> no cross-thread sync needed)
        const float4 a0 = buf[phase][wib][0][lane];
        const float4 a1 = buf[phase][wib][1][lane];
        const float4 a2 = buf[phase][wib][2][lane];
        const float4 a3 = buf[phase][wib][3][lane];
        const float4 a4 = buf[phase][wib][4][lane];
        const float4 a5 = buf[phase][wib][5][lane];

        float4 r;
        r.x = w0c * a0.x + w1c * a1.x + w2c * a2.x;
        r.y = w0c * a0.y + w1c * a1.y + w2c * a2.y;
        r.z = w0c * a0.z + w1c * a1.z + w2c * a2.z;
        r.w = w0c * a0.w + w1c * a1.w + w2c * a2.w;
        stcs(out + ((size_t)(2 * bp_c) * M_DIM + m_c) * C_VEC + lane, r);

        r.x = w0c * a3.x + w1c * a4.x + w2c * a5.x;
        r.y = w0c * a3.y + w1c * a4.y + w2c * a5.y;
        r.z = w0c * a3.z + w1c * a4.z + w2c * a5.z;
        r.w = w0c * a3.w + w1c * a4.w + w2c * a5.w;
        stcs(out + ((size_t)(2 * bp_c + 1) * M_DIM + m_c) * C_VEC + lane, r);

        cur = nxt; bp_c = bp_n; m_c = m_n;
        w0c = w0n; w1c = w1n; w2c = w2n;
        phase ^= 1;
    }
}

extern "C" void kernel_launch(void* const* d_in, const int* in_sizes, int n_in,
                              void* d_out, int out_size)
{
    const float4* x    = (const float4*)d_in[0];
    const int*    cols = (const int*)d_in[1];
    const float*  vals = (const float*)d_in[2];
    float4*       out  = (float4*)d_out;

    mesh_sampling_kernel<<<NBLOCKS, THREADS>>>(x, cols, vals, out);
}